// round 1
// baseline (speedup 1.0000x reference)
#include <cuda_runtime.h>

#define NN 30000
#define EE 480000

// Scratch (device globals -- no allocation allowed)
__device__ float4 g_aggA[NN * 32];   // per node, 32 channels x {s_a, v_a.xyz}
__device__ float4 g_aggB[NN * 32];   // per node, 32 channels x {s_b, v_b.xyz}
__device__ float  g_x0[NN * 32];
__device__ float  g_x1[NN * 96];

// ---------------------------------------------------------------------------
__global__ void zero_kernel() {
    int i = blockIdx.x * blockDim.x + threadIdx.x;
    int stride = gridDim.x * blockDim.x;
    float4 z = make_float4(0.f, 0.f, 0.f, 0.f);
    for (int k = i; k < NN * 32; k += stride) {
        g_aggA[k] = z;
        g_aggB[k] = z;
    }
}

// ---------------------------------------------------------------------------
// x0 = node_s @ W1_0 * inv_m ; x1[n,w,d] = sum_u node_v[n,u,d]*W1_1[u,w]*inv_m
__global__ void node_pre_kernel(const float* __restrict__ node_s,
                                const float* __restrict__ node_v,
                                const float* __restrict__ W1_0,
                                const float* __restrict__ W1_1) {
    __shared__ float w0s[1024], w1s[1024];
    for (int i = threadIdx.x; i < 1024; i += blockDim.x) {
        w0s[i] = W1_0[i];
        w1s[i] = W1_1[i];
    }
    __syncthreads();
    int warp = (blockIdx.x * blockDim.x + threadIdx.x) >> 5;
    int lane = threadIdx.x & 31;
    if (warp >= NN) return;

    float s  = node_s[warp * 32 + lane];
    float v0 = node_v[warp * 96 + lane * 3 + 0];
    float v1 = node_v[warp * 96 + lane * 3 + 1];
    float v2 = node_v[warp * 96 + lane * 3 + 2];

    float x0 = 0.f, a0 = 0.f, a1 = 0.f, a2 = 0.f;
#pragma unroll
    for (int u = 0; u < 32; u++) {
        float su  = __shfl_sync(0xffffffffu, s,  u);
        float vu0 = __shfl_sync(0xffffffffu, v0, u);
        float vu1 = __shfl_sync(0xffffffffu, v1, u);
        float vu2 = __shfl_sync(0xffffffffu, v2, u);
        float w0 = w0s[u * 32 + lane];
        float w1 = w1s[u * 32 + lane];
        x0 = fmaf(su, w0, x0);
        a0 = fmaf(vu0, w1, a0);
        a1 = fmaf(vu1, w1, a1);
        a2 = fmaf(vu2, w1, a2);
    }
    const float inv_m = 0.17677669529663687f;  // 1/sqrt(32)
    g_x0[warp * 32 + lane]         = x0 * inv_m;
    g_x1[warp * 96 + lane * 3 + 0] = a0 * inv_m;
    g_x1[warp * 96 + lane * 3 + 1] = a1 * inv_m;
    g_x1[warp * 96 + lane * 3 + 2] = a2 * inv_m;
}

// ---------------------------------------------------------------------------
__device__ __forceinline__ void red_v4(float4* addr, float a, float b, float c, float d) {
    asm volatile("red.global.add.v4.f32 [%0], {%1,%2,%3,%4};"
                 :: "l"(addr), "f"(a), "f"(b), "f"(c), "f"(d) : "memory");
}

// One warp per edge; lane = channel u (0..31).
__global__ void edge_kernel(const float* __restrict__ edge_attr,
                            const float* __restrict__ edge_scalars,
                            const float* __restrict__ Wfc1,
                            const float* __restrict__ Wfc2,
                            const int*   __restrict__ edge_src,
                            const int*   __restrict__ edge_dst) {
    __shared__ float fc1s[64], fc2s[1024];
    for (int i = threadIdx.x; i < 64; i += blockDim.x) fc1s[i] = Wfc1[i];
    for (int i = threadIdx.x; i < 1024; i += blockDim.x) fc2s[i] = Wfc2[i];
    __syncthreads();

    int e = (blockIdx.x * blockDim.x + threadIdx.x) >> 5;
    int lane = threadIdx.x & 31;
    if (e >= EE) return;

    const float inv8 = 0.35355339059327373f;  // 1/sqrt(8)

    // --- h = ssp(es @ Wfc1 * inv8) : lanes 0..7, one output each ---
    float hv = 0.f;
    if (lane < 8) {
        float acc = 0.f;
#pragma unroll
        for (int k = 0; k < 8; k++)
            acc = fmaf(edge_scalars[e * 8 + k], fc1s[k * 8 + lane], acc);
        acc *= inv8;
        // softplus(acc) - log(2), numerically stable
        float ex = __expf(-fabsf(acc));
        hv = fmaxf(acc, 0.f) + log1pf(ex) - 0.6931471805599453f;
    }
    float h[8];
#pragma unroll
    for (int j = 0; j < 8; j++) h[j] = __shfl_sync(0xffffffffu, hv, j);

    // --- w = h @ Wfc2 * inv8 ; each lane needs w00,w01,w10,w11 at col lane ---
    float w00 = 0.f, w01 = 0.f, w10 = 0.f, w11 = 0.f;
#pragma unroll
    for (int j = 0; j < 8; j++) {
        const float* r = &fc2s[j * 128 + lane];
        w00 = fmaf(h[j], r[0],  w00);
        w01 = fmaf(h[j], r[32], w01);
        w10 = fmaf(h[j], r[64], w10);
        w11 = fmaf(h[j], r[96], w11);
    }
    w00 *= inv8; w01 *= inv8; w10 *= inv8; w11 *= inv8;

    int dstn = edge_dst[e];
    int srcn = edge_src[e];

    float x0 = g_x0[dstn * 32 + lane];
    float y0 = g_x1[dstn * 96 + lane * 3 + 0];
    float y1 = g_x1[dstn * 96 + lane * 3 + 1];
    float y2 = g_x1[dstn * 96 + lane * 3 + 2];

    float sh0 = edge_attr[e * 4 + 0];
    float sh1 = edge_attr[e * 4 + 1];
    float sh2 = edge_attr[e * 4 + 2];
    float sh3 = edge_attr[e * 4 + 3];

    const float INV_SQRT3 = 0.5773502691896258f;
    float s_a = w00 * x0 * sh0;
    float dot = fmaf(y0, sh1, fmaf(y1, sh2, y2 * sh3));
    float s_b = w11 * dot * INV_SQRT3;
    float p = w01 * x0;     // v_a[d] = p * sh[d]
    float q = w10 * sh0;    // v_b[d] = q * y[d]

    red_v4(&g_aggA[srcn * 32 + lane], s_a, p * sh1, p * sh2, p * sh3);
    red_v4(&g_aggB[srcn * 32 + lane], s_b, q * y0, q * y1, q * y2);
}

// ---------------------------------------------------------------------------
// One block (128 threads) per node: out = agg @ W2 * c + selfconnection
__global__ void node_post_kernel(const float* __restrict__ node_s,
                                 const float* __restrict__ node_v,
                                 const float* __restrict__ node_attr,
                                 const float* __restrict__ W2_0,
                                 const float* __restrict__ W2_1,
                                 const float* __restrict__ Wsc0,
                                 const float* __restrict__ Wsc1,
                                 float* __restrict__ out) {
    int n = blockIdx.x;
    int tid = threadIdx.x;
    __shared__ float A0[1024], A1[1024];
    __shared__ float sS[32], sV[96], sAtt[8], sA[128], sB[128];

    if (tid < 32) sS[tid] = node_s[n * 32 + tid];
    if (tid < 96) sV[tid] = node_v[n * 96 + tid];
    if (tid < 8)  sAtt[tid] = node_attr[n * 8 + tid];
    {
        const float* aggA = (const float*)g_aggA;
        const float* aggB = (const float*)g_aggB;
        sA[tid] = aggA[n * 128 + tid];
        sB[tid] = aggB[n * 128 + tid];
    }
    __syncthreads();

    // A[u][w] = sum_v attr[v] * Wsc[u][v][w]
    for (int i = tid; i < 2048; i += 128) {
        int idx = i & 1023;
        const float* W = (i < 1024) ? Wsc0 : Wsc1;
        int u = idx >> 5, w = idx & 31;
        float acc = 0.f;
#pragma unroll
        for (int v = 0; v < 8; v++)
            acc = fmaf(sAtt[v], W[u * 256 + v * 32 + w], acc);
        if (i < 1024) A0[idx] = acc; else A1[idx] = acc;
    }
    __syncthreads();

    const float c_agg = 0.03125f;  // 1/sqrt(64) * 1/sqrt(16)
    const float c_sc  = 0.0625f;   // 1/sqrt(32*8)

    if (tid < 32) {
        int w = tid;
        float acc = 0.f, sc = 0.f;
#pragma unroll
        for (int u = 0; u < 32; u++) {
            acc = fmaf(sA[u * 4 + 0], W2_0[u * 32 + w], acc);
            acc = fmaf(sB[u * 4 + 0], W2_0[(32 + u) * 32 + w], acc);
            sc  = fmaf(sS[u], A0[u * 32 + w], sc);
        }
        out[n * 128 + w] = acc * c_agg + sc * c_sc;
    } else {
        int idx = tid - 32;
        int w = idx / 3, d = idx % 3;
        float acc = 0.f, sc = 0.f;
#pragma unroll
        for (int u = 0; u < 32; u++) {
            acc = fmaf(sA[u * 4 + 1 + d], W2_1[u * 32 + w], acc);
            acc = fmaf(sB[u * 4 + 1 + d], W2_1[(32 + u) * 32 + w], acc);
            sc  = fmaf(sV[u * 3 + d], A1[u * 32 + w], sc);
        }
        out[n * 128 + 32 + idx] = acc * c_agg + sc * c_sc;
    }
}

// ---------------------------------------------------------------------------
extern "C" void kernel_launch(void* const* d_in, const int* in_sizes, int n_in,
                              void* d_out, int out_size) {
    const float* node_s       = (const float*)d_in[0];
    const float* node_v       = (const float*)d_in[1];
    const float* node_attr    = (const float*)d_in[2];
    const float* edge_attr    = (const float*)d_in[3];
    const float* edge_scalars = (const float*)d_in[4];
    const float* W1_0         = (const float*)d_in[5];
    const float* W1_1         = (const float*)d_in[6];
    const float* Wfc1         = (const float*)d_in[7];
    const float* Wfc2         = (const float*)d_in[8];
    const float* W2_0         = (const float*)d_in[9];
    const float* W2_1         = (const float*)d_in[10];
    const float* Wsc0         = (const float*)d_in[11];
    const float* Wsc1         = (const float*)d_in[12];
    const int*   edge_src     = (const int*)d_in[13];
    const int*   edge_dst     = (const int*)d_in[14];
    float* out = (float*)d_out;

    zero_kernel<<<2048, 256>>>();
    node_pre_kernel<<<(NN * 32 + 255) / 256, 256>>>(node_s, node_v, W1_0, W1_1);
    edge_kernel<<<(EE * 32 + 255) / 256, 256>>>(edge_attr, edge_scalars, Wfc1, Wfc2,
                                                edge_src, edge_dst);
    node_post_kernel<<<NN, 128>>>(node_s, node_v, node_attr, W2_0, W2_1,
                                  Wsc0, Wsc1, out);
}